// round 2
// baseline (speedup 1.0000x reference)
#include <cuda_runtime.h>
#include <cstdint>

#define H    512
#define G4   2048
#define SEQL 1024
#define EMB  300
#define NCTA 64
#define TPB  256

// Scratch (no allocations allowed): 8 MB gate-precompute + 4 MB tagged-h ring.
__device__ float              g_xg[SEQL * G4];
__device__ unsigned long long g_htag[SEQL * H];

// ---------------------------------------------------------------------------
// Kernel 1: xg[t][row] = (b_ih[row]+b_hh[row]) + sum_e emb[tok[t]][e]*W_ih[row][e]
// 64x64 output tile per block, 4x4 micro-tile per thread, K-chunks of 16.
// ---------------------------------------------------------------------------
#define TK 16
__global__ __launch_bounds__(256) void xgemm_kernel(
    const int* __restrict__ tokens,
    const float* __restrict__ emb,
    const float* __restrict__ Wih,
    const float* __restrict__ bih,
    const float* __restrict__ bhh)
{
    __shared__ float Ws[64][TK + 1];
    __shared__ float Xs[64][TK + 1];
    __shared__ int   toks[64];

    const int row0 = blockIdx.x * 64;
    const int t0   = blockIdx.y * 64;
    const int tid  = threadIdx.x;
    const int tx = tid & 15, ty = tid >> 4;

    if (tid < 64) toks[tid] = tokens[t0 + tid];
    __syncthreads();

    float acc[4][4];
#pragma unroll
    for (int i = 0; i < 4; i++)
#pragma unroll
        for (int j = 0; j < 4; j++) acc[i][j] = 0.f;

    const int kk = tid & 15;
    const int ib = tid >> 4;

    for (int k0 = 0; k0 < EMB; k0 += TK) {
#pragma unroll
        for (int q = 0; q < 4; q++) {
            int i = ib + q * 16;
            int e = k0 + kk;
            // clamp keeps the address in-bounds; the product is zeroed via Xs.
            long widx = (long)(row0 + i) * EMB + (e < EMB ? e : EMB - 1);
            Ws[i][kk] = Wih[widx];
            Xs[i][kk] = (e < EMB) ? emb[(long)toks[i] * EMB + e] : 0.f;
        }
        __syncthreads();
#pragma unroll
        for (int k = 0; k < TK; k++) {
            float a[4], x[4];
#pragma unroll
            for (int i = 0; i < 4; i++) a[i] = Ws[tx * 4 + i][k];
#pragma unroll
            for (int j = 0; j < 4; j++) x[j] = Xs[ty * 4 + j][k];
#pragma unroll
            for (int i = 0; i < 4; i++)
#pragma unroll
                for (int j = 0; j < 4; j++)
                    acc[i][j] += a[i] * x[j];
        }
        __syncthreads();
    }

#pragma unroll
    for (int i = 0; i < 4; i++) {
        int row = row0 + tx * 4 + i;
        float bias = bih[row] + bhh[row];
#pragma unroll
        for (int j = 0; j < 4; j++) {
            int t = t0 + ty * 4 + j;
            g_xg[(long)t * G4 + row] = acc[i][j] + bias;
        }
    }
}

// ---------------------------------------------------------------------------
// Kernel 2: persistent LSTM recurrence.
// 64 CTAs (all co-resident), CTA b owns hidden k in [8b,8b+8) and the 32 gate
// rows {g*512 + 8b + kk}. W_hh lives entirely in registers (64 fp32/thread).
// h broadcast: 8-byte (tag,value) STG per element; consumers spin on the 16B
// they need via ld.volatile — data+flag in one L2 transaction.
// ---------------------------------------------------------------------------
__global__ __launch_bounds__(TPB, 1) void lstm_kernel(
    const int* __restrict__ tokens,
    const float* __restrict__ h0,
    const float* __restrict__ c0,
    const float* __restrict__ Whh,
    float* __restrict__ out)
{
    __shared__ float h_s[H + H / 16];   // pad 1 per 16 -> conflict-free 17-stride reads
    __shared__ float gates_s[32];
    __shared__ int   toks[SEQL];

    const int b    = blockIdx.x;
    const int tid  = threadIdx.x;
    const int w    = tid >> 5;
    const int lane = tid & 31;

    for (int i = tid; i < SEQL; i += TPB) toks[i] = tokens[i];

    // Warp w -> gate (w>>1), kk base 4*(w&1); lane -> K-segment [16*lane, 16*lane+16).
    float wreg[4][16];
    int grow[4];
#pragma unroll
    for (int i = 0; i < 4; i++) {
        grow[i] = (w >> 1) * H + b * 8 + 4 * (w & 1) + i;
#pragma unroll
        for (int j = 0; j < 16; j++)
            wreg[i][j] = Whh[(long)grow[i] * H + lane * 16 + j];
    }

    float c_reg = 0.f, h_last = 0.f, out_reg = 0.f;
    if (tid < 8) {
        c_reg  = c0[b * 8 + tid];
        h_last = h0[b * 8 + tid];
    }

    unsigned long long* htag = g_htag;

    for (int t = 0; t < SEQL; t++) {
        // Prefetch this step's xg rows (independent of h) while we wait.
        float xgv[4] = {0.f, 0.f, 0.f, 0.f};
        if (lane == 0) {
#pragma unroll
            for (int i = 0; i < 4; i++)
                xgv[i] = g_xg[(long)t * G4 + grow[i]];
        }

        // Acquire h_{t-1} into padded smem.
        if (t == 0) {
            int k0 = 2 * tid, k1 = 2 * tid + 1;
            h_s[k0 + (k0 >> 4)] = h0[k0];
            h_s[k1 + (k1 >> 4)] = h0[k1];
        } else {
            const unsigned long long* p = htag + (long)(t - 1) * H + 2 * tid;
            unsigned long long v0, v1;
            unsigned tag = (unsigned)t;  // written as t_prev+1 = t
            do {
                asm volatile("ld.volatile.global.v2.u64 {%0,%1},[%2];"
                             : "=l"(v0), "=l"(v1) : "l"(p));
            } while ((unsigned)(v0 >> 32) != tag || (unsigned)(v1 >> 32) != tag);
            int k0 = 2 * tid, k1 = 2 * tid + 1;
            h_s[k0 + (k0 >> 4)] = __uint_as_float((unsigned)v0);
            h_s[k1 + (k1 >> 4)] = __uint_as_float((unsigned)v1);
        }
        __syncthreads();

        // Partial dots: 4 rows x 16 K-elements per thread, all weights in regs.
        float acc0 = 0.f, acc1 = 0.f, acc2 = 0.f, acc3 = 0.f;
#pragma unroll
        for (int j = 0; j < 16; j++) {
            float hv = h_s[17 * lane + j];
            acc0 += wreg[0][j] * hv;
            acc1 += wreg[1][j] * hv;
            acc2 += wreg[2][j] * hv;
            acc3 += wreg[3][j] * hv;
        }
#pragma unroll
        for (int off = 16; off > 0; off >>= 1) {
            acc0 += __shfl_xor_sync(0xffffffffu, acc0, off);
            acc1 += __shfl_xor_sync(0xffffffffu, acc1, off);
            acc2 += __shfl_xor_sync(0xffffffffu, acc2, off);
            acc3 += __shfl_xor_sync(0xffffffffu, acc3, off);
        }
        if (lane == 0) {
            gates_s[w * 4 + 0] = acc0 + xgv[0];
            gates_s[w * 4 + 1] = acc1 + xgv[1];
            gates_s[w * 4 + 2] = acc2 + xgv[2];
            gates_s[w * 4 + 3] = acc3 + xgv[3];
        }
        __syncthreads();

        if (tid < 8) {
            int k = tid;
            float gi = gates_s[k];
            float gf = gates_s[8 + k];
            float gg = gates_s[16 + k];
            float go = gates_s[24 + k];
            float si = 1.f / (1.f + __expf(-gi));
            float sf = 1.f / (1.f + __expf(-gf));
            float so = 1.f / (1.f + __expf(-go));
            float tg = tanhf(gg);
            float c_new = sf * c_reg + si * tg;
            float h_new = so * tanhf(c_new);
            if (toks[t] != 1) {     // PAD_IDX == 1
                c_reg  = c_new;
                h_last = h_new;
                out_reg = h_new;
            }
            unsigned long long v =
                ((unsigned long long)(unsigned)(t + 1) << 32) |
                (unsigned long long)__float_as_uint(h_last);
            htag[(long)t * H + b * 8 + k] = v;
        }
        __syncthreads();   // protect h_s/gates_s against next-step overwrite
    }

    if (tid < 8) {
        out[b * 8 + tid]         = out_reg;  // out
        out[H + b * 8 + tid]     = h_last;   // h
        out[2 * H + b * 8 + tid] = c_reg;    // c
    }
}

extern "C" void kernel_launch(void* const* d_in, const int* in_sizes, int n_in,
                              void* d_out, int out_size)
{
    const int*   tokens = (const int*)  d_in[0];
    const float* h0     = (const float*)d_in[1];
    const float* c0     = (const float*)d_in[2];
    const float* emb    = (const float*)d_in[3];
    const float* Wih    = (const float*)d_in[4];
    const float* Whh    = (const float*)d_in[5];
    const float* bih    = (const float*)d_in[6];
    const float* bhh    = (const float*)d_in[7];
    float* out = (float*)d_out;

    // Reset the tag buffer every launch (deterministic across replays).
    void* htag_ptr = nullptr;
    cudaGetSymbolAddress(&htag_ptr, g_htag);
    cudaMemsetAsync(htag_ptr, 0, sizeof(unsigned long long) * SEQL * H);

    dim3 g1(G4 / 64, SEQL / 64);
    xgemm_kernel<<<g1, 256>>>(tokens, emb, Wih, bih, bhh);
    lstm_kernel<<<NCTA, TPB>>>(tokens, h0, c0, Whh, out);
}